// round 5
// baseline (speedup 1.0000x reference)
#include <cuda_runtime.h>

#define NB 8
#define NV 100000
#define NF 200000
#define BN (NB * NV)
#define TOTF (NB * NF)

// scratch (no cudaMalloc allowed)
__device__ float g_deg[BN];
__device__ int g_is32;   // 1 if F is int32, 0 if int64

// Detect F element dtype: if data is really int64, every 64-bit word is a
// valid index in [0, NV). If it's int32, most 64-bit words pack two indices
// -> value >= NV (or negative). Deterministic: same input -> same flag.
__global__ void detect_k(const long long* __restrict__ F64, int nwords) {
    if (blockIdx.x == 0 && threadIdx.x == 0) {
        int is32 = 0;
        int n = nwords < 1024 ? nwords : 1024;
        for (int i = 0; i < n; i++) {
            long long v = F64[i];
            if (v < 0 || v >= NV) { is32 = 1; break; }
        }
        g_is32 = is32;
    }
}

__global__ void zero_k(float* __restrict__ out) {
    int stride = gridDim.x * blockDim.x;
    int i = blockIdx.x * blockDim.x + threadIdx.x;
    for (int j = i; j < BN * 3; j += stride) out[j] = 0.0f;
    for (int j = i; j < BN; j += stride) g_deg[j] = 0.0f;
}

__device__ __forceinline__ int clampi(int v, int lo, int hi) {
    return v < lo ? lo : (v > hi ? hi : v);
}

__global__ void __launch_bounds__(256) face_k(const float* __restrict__ V,
                                              const void* __restrict__ Fraw,
                                              float* __restrict__ out) {
    int t = blockIdx.x * blockDim.x + threadIdx.x;
    if (t >= TOTF) return;
    int b = t / NF;
    int base = b * NV;

    int f0, f1, f2;
    if (g_is32) {
        const int* fp = (const int*)Fraw + (size_t)t * 3;
        f0 = fp[0]; f1 = fp[1]; f2 = fp[2];
    } else {
        const long long* fp = (const long long*)Fraw + (size_t)t * 3;
        f0 = (int)fp[0]; f1 = (int)fp[1]; f2 = (int)fp[2];
    }
    // safety clamp (no-op for valid input)
    f0 = clampi(f0, 0, NV - 1);
    f1 = clampi(f1, 0, NV - 1);
    f2 = clampi(f2, 0, NV - 1);

    int i0 = base + f0, i1 = base + f1, i2 = base + f2;

    const float* p0 = V + (size_t)i0 * 3;
    const float* p1 = V + (size_t)i1 * 3;
    const float* p2 = V + (size_t)i2 * 3;
    float x0 = p0[0], y0 = p0[1], z0 = p0[2];
    float x1 = p1[0], y1 = p1[1], z1 = p1[2];
    float x2 = p2[0], y2 = p2[1], z2 = p2[2];

    // squared edge lengths (reference: l1=|v1-v2|, l2=|v2-v0|, l3=|v0-v1|)
    float ax = x1 - x2, ay = y1 - y2, az = z1 - z2;
    float bx = x2 - x0, by = y2 - y0, bz = z2 - z0;
    float cx = x0 - x1, cy = y0 - y1, cz = z0 - z1;
    float d1 = ax * ax + ay * ay + az * az;
    float d2 = bx * bx + by * by + bz * bz;
    float d3 = cx * cx + cy * cy + cz * cz;
    float l1 = sqrtf(d1), l2 = sqrtf(d2), l3 = sqrtf(d3);
    float sp = 0.5f * (l1 + l2 + l3);
    float inside = sp * (sp - l1) * (sp - l2) * (sp - l3);
    inside = fmaxf(inside, 0.0f);
    float A = 2.0f * sqrtf(inside);
    float inv = 0.25f / (A + 1e-10f);
    if (A == 0.0f) inv = 0.0f;

    float w23 = (d2 + d3 - d1) * inv;  // edge (v1,v2)
    float w31 = (d1 + d3 - d2) * inv;  // edge (v2,v0)
    float w12 = (d1 + d2 - d3) * inv;  // edge (v0,v1)

    // per-vertex folded contributions (2 edges touch each vertex)
    float* o0 = out + (size_t)i0 * 3;
    float* o1 = out + (size_t)i1 * 3;
    float* o2 = out + (size_t)i2 * 3;

    atomicAdd(&o0[0], w31 * x2 + w12 * x1);
    atomicAdd(&o0[1], w31 * y2 + w12 * y1);
    atomicAdd(&o0[2], w31 * z2 + w12 * z1);
    atomicAdd(&g_deg[i0], w31 + w12);

    atomicAdd(&o1[0], w23 * x2 + w12 * x0);
    atomicAdd(&o1[1], w23 * y2 + w12 * y0);
    atomicAdd(&o1[2], w23 * z2 + w12 * z0);
    atomicAdd(&g_deg[i1], w23 + w12);

    atomicAdd(&o2[0], w23 * x1 + w31 * x0);
    atomicAdd(&o2[1], w23 * y1 + w31 * y0);
    atomicAdd(&o2[2], w23 * z1 + w31 * z0);
    atomicAdd(&g_deg[i2], w23 + w31);
}

__global__ void fin_k(const float* __restrict__ V, float* __restrict__ out) {
    int j = blockIdx.x * blockDim.x + threadIdx.x;
    if (j < BN * 3) {
        out[j] -= g_deg[j / 3] * V[j];
    }
}

extern "C" void kernel_launch(void* const* d_in, const int* in_sizes, int n_in,
                              void* d_out, int out_size) {
    // Robust slot selection: V has BN*3 = 2.4M elements, F has TOTF*3 = 4.8M.
    const float* V;
    const void* F;
    int f_elems;
    if (in_sizes[0] == BN * 3) {
        V = (const float*)d_in[0];
        F = d_in[1];
        f_elems = in_sizes[1];
    } else {
        V = (const float*)d_in[1];
        F = d_in[0];
        f_elems = in_sizes[0];
    }
    float* out = (float*)d_out;

    // If F were int32, f_elems int32 values occupy f_elems/2 64-bit words.
    detect_k<<<1, 32>>>((const long long*)F, f_elems / 2);
    zero_k<<<2048, 256>>>(out);
    face_k<<<(TOTF + 255) / 256, 256>>>(V, F, out);
    fin_k<<<(BN * 3 + 255) / 256, 256>>>(V, out);
}

// round 6
// speedup vs baseline: 2.0099x; 2.0099x over previous
#include <cuda_runtime.h>

#define NB 8
#define NV 100000
#define NF 200000
#define BN (NB * NV)
#define TOTF (NB * NF)

// scratch: per-vertex accumulator (x, y, z, deg) — 12.8 MB, L2-resident
__device__ float4 g_acc[BN];
__device__ int g_is32;   // 1 if F is int32, 0 if int64

// Detect F element dtype (deterministic).
__global__ void detect_k(const long long* __restrict__ F64, int nwords) {
    if (blockIdx.x == 0 && threadIdx.x == 0) {
        int is32 = 0;
        int n = nwords < 1024 ? nwords : 1024;
        for (int i = 0; i < n; i++) {
            long long v = F64[i];
            if (v < 0 || v >= NV) { is32 = 1; break; }
        }
        g_is32 = is32;
    }
}

__global__ void zero_k() {
    int stride = gridDim.x * blockDim.x;
    int i = blockIdx.x * blockDim.x + threadIdx.x;
    float4 z = make_float4(0.f, 0.f, 0.f, 0.f);
    for (int j = i; j < BN; j += stride) g_acc[j] = z;
}

__device__ __forceinline__ int clampi(int v, int lo, int hi) {
    return v < lo ? lo : (v > hi ? hi : v);
}

__device__ __forceinline__ void red_v4(float4* addr, float x, float y, float z, float w) {
    asm volatile("red.global.add.v4.f32 [%0], {%1, %2, %3, %4};"
                 :: "l"(addr), "f"(x), "f"(y), "f"(z), "f"(w)
                 : "memory");
}

__global__ void __launch_bounds__(256) face_k(const float* __restrict__ V,
                                              const void* __restrict__ Fraw) {
    int t = blockIdx.x * blockDim.x + threadIdx.x;
    if (t >= TOTF) return;
    int b = t / NF;
    int base = b * NV;

    int f0, f1, f2;
    if (g_is32) {
        const int* fp = (const int*)Fraw + (size_t)t * 3;
        f0 = fp[0]; f1 = fp[1]; f2 = fp[2];
    } else {
        const long long* fp = (const long long*)Fraw + (size_t)t * 3;
        f0 = (int)fp[0]; f1 = (int)fp[1]; f2 = (int)fp[2];
    }
    f0 = clampi(f0, 0, NV - 1);
    f1 = clampi(f1, 0, NV - 1);
    f2 = clampi(f2, 0, NV - 1);

    int i0 = base + f0, i1 = base + f1, i2 = base + f2;

    const float* p0 = V + (size_t)i0 * 3;
    const float* p1 = V + (size_t)i1 * 3;
    const float* p2 = V + (size_t)i2 * 3;
    float x0 = p0[0], y0 = p0[1], z0 = p0[2];
    float x1 = p1[0], y1 = p1[1], z1 = p1[2];
    float x2 = p2[0], y2 = p2[1], z2 = p2[2];

    // squared edge lengths (reference: l1=|v1-v2|, l2=|v2-v0|, l3=|v0-v1|)
    float ax = x1 - x2, ay = y1 - y2, az = z1 - z2;
    float bx = x2 - x0, by = y2 - y0, bz = z2 - z0;
    float cx = x0 - x1, cy = y0 - y1, cz = z0 - z1;
    float d1 = ax * ax + ay * ay + az * az;
    float d2 = bx * bx + by * by + bz * bz;
    float d3 = cx * cx + cy * cy + cz * cz;
    float l1 = sqrtf(d1), l2 = sqrtf(d2), l3 = sqrtf(d3);
    float sp = 0.5f * (l1 + l2 + l3);
    float inside = sp * (sp - l1) * (sp - l2) * (sp - l3);
    inside = fmaxf(inside, 0.0f);
    float A = 2.0f * sqrtf(inside);
    float inv = 0.25f / (A + 1e-10f);
    if (A == 0.0f) inv = 0.0f;

    float w23 = (d2 + d3 - d1) * inv;  // edge (v1,v2)
    float w31 = (d1 + d3 - d2) * inv;  // edge (v2,v0)
    float w12 = (d1 + d2 - d3) * inv;  // edge (v0,v1)

    // per-vertex folded contributions, one v4 reduction each:
    // v0 += (w31*P2 + w12*P1, w31+w12)
    // v1 += (w23*P2 + w12*P0, w23+w12)
    // v2 += (w23*P1 + w31*P0, w23+w31)
    red_v4(&g_acc[i0], w31 * x2 + w12 * x1, w31 * y2 + w12 * y1,
                       w31 * z2 + w12 * z1, w31 + w12);
    red_v4(&g_acc[i1], w23 * x2 + w12 * x0, w23 * y2 + w12 * y0,
                       w23 * z2 + w12 * z0, w23 + w12);
    red_v4(&g_acc[i2], w23 * x1 + w31 * x0, w23 * y1 + w31 * y0,
                       w23 * z1 + w31 * z0, w23 + w31);
}

// out[v] = acc[v].xyz - acc[v].w * V[v]
__global__ void fin_k(const float* __restrict__ V, float* __restrict__ out) {
    int j = blockIdx.x * blockDim.x + threadIdx.x;
    if (j < BN * 3) {
        int v = j / 3;
        int c = j - v * 3;
        float4 a = g_acc[v];
        float comp = (c == 0) ? a.x : (c == 1) ? a.y : a.z;
        out[j] = comp - a.w * V[j];
    }
}

extern "C" void kernel_launch(void* const* d_in, const int* in_sizes, int n_in,
                              void* d_out, int out_size) {
    // Robust slot selection: V has BN*3 = 2.4M elements, F has TOTF*3 = 4.8M.
    const float* V;
    const void* F;
    int f_elems;
    if (in_sizes[0] == BN * 3) {
        V = (const float*)d_in[0];
        F = d_in[1];
        f_elems = in_sizes[1];
    } else {
        V = (const float*)d_in[1];
        F = d_in[0];
        f_elems = in_sizes[0];
    }
    float* out = (float*)d_out;

    detect_k<<<1, 32>>>((const long long*)F, f_elems / 2);
    zero_k<<<1024, 256>>>();
    face_k<<<(TOTF + 255) / 256, 256>>>(V, F);
    fin_k<<<(BN * 3 + 255) / 256, 256>>>(V, out);
}

// round 7
// speedup vs baseline: 2.2709x; 1.1299x over previous
#include <cuda_runtime.h>

#define NB 8
#define NV 100000
#define NF 200000
#define BN (NB * NV)
#define TOTF (NB * NF)

// scratch: per-vertex accumulator (x, y, z, deg) — 12.8 MB, L2-resident
__device__ float4 g_acc[BN];
// padded, 16B-aligned copy of V for single-LDG.128 gathers
__device__ float4 g_V4[BN];
__device__ int g_is32;   // 1 if F is int32, 0 if int64

// Detect F element dtype (deterministic).
__global__ void detect_k(const long long* __restrict__ F64, int nwords) {
    if (blockIdx.x == 0 && threadIdx.x == 0) {
        int is32 = 0;
        int n = nwords < 1024 ? nwords : 1024;
        for (int i = 0; i < n; i++) {
            long long v = F64[i];
            if (v < 0 || v >= NV) { is32 = 1; break; }
        }
        g_is32 = is32;
    }
}

// Fused prep: zero accumulators + pad V (B,N,3) into float4 staging.
__global__ void prep_k(const float* __restrict__ V) {
    int stride = gridDim.x * blockDim.x;
    for (int v = blockIdx.x * blockDim.x + threadIdx.x; v < BN; v += stride) {
        const float* p = V + (size_t)v * 3;
        g_V4[v] = make_float4(p[0], p[1], p[2], 0.f);
        g_acc[v] = make_float4(0.f, 0.f, 0.f, 0.f);
    }
}

__device__ __forceinline__ int clampi(int v, int lo, int hi) {
    return v < lo ? lo : (v > hi ? hi : v);
}

__device__ __forceinline__ void red_v4(float4* addr, float x, float y, float z, float w) {
    asm volatile("red.global.add.v4.f32 [%0], {%1, %2, %3, %4};"
                 :: "l"(addr), "f"(x), "f"(y), "f"(z), "f"(w)
                 : "memory");
}

__global__ void __launch_bounds__(256) face_k(const void* __restrict__ Fraw) {
    int t = blockIdx.x * blockDim.x + threadIdx.x;
    if (t >= TOTF) return;
    int b = t / NF;
    int base = b * NV;

    int f0, f1, f2;
    if (g_is32) {
        const int* fp = (const int*)Fraw + (size_t)t * 3;
        f0 = fp[0]; f1 = fp[1]; f2 = fp[2];
    } else {
        const long long* fp = (const long long*)Fraw + (size_t)t * 3;
        f0 = (int)fp[0]; f1 = (int)fp[1]; f2 = (int)fp[2];
    }
    f0 = clampi(f0, 0, NV - 1);
    f1 = clampi(f1, 0, NV - 1);
    f2 = clampi(f2, 0, NV - 1);

    int i0 = base + f0, i1 = base + f1, i2 = base + f2;

    float4 P0 = __ldg(&g_V4[i0]);
    float4 P1 = __ldg(&g_V4[i1]);
    float4 P2 = __ldg(&g_V4[i2]);
    float x0 = P0.x, y0 = P0.y, z0 = P0.z;
    float x1 = P1.x, y1 = P1.y, z1 = P1.z;
    float x2 = P2.x, y2 = P2.y, z2 = P2.z;

    // squared edge lengths (reference: l1=|v1-v2|, l2=|v2-v0|, l3=|v0-v1|)
    float ax = x1 - x2, ay = y1 - y2, az = z1 - z2;
    float bx = x2 - x0, by = y2 - y0, bz = z2 - z0;
    float cx = x0 - x1, cy = y0 - y1, cz = z0 - z1;
    float d1 = ax * ax + ay * ay + az * az;
    float d2 = bx * bx + by * by + bz * bz;
    float d3 = cx * cx + cy * cy + cz * cz;
    float l1 = sqrtf(d1), l2 = sqrtf(d2), l3 = sqrtf(d3);
    float sp = 0.5f * (l1 + l2 + l3);
    float inside = sp * (sp - l1) * (sp - l2) * (sp - l3);
    inside = fmaxf(inside, 0.0f);
    float A = 2.0f * sqrtf(inside);
    float inv = 0.25f / (A + 1e-10f);
    if (A == 0.0f) inv = 0.0f;

    float w23 = (d2 + d3 - d1) * inv;  // edge (v1,v2)
    float w31 = (d1 + d3 - d2) * inv;  // edge (v2,v0)
    float w12 = (d1 + d2 - d3) * inv;  // edge (v0,v1)

    red_v4(&g_acc[i0], w31 * x2 + w12 * x1, w31 * y2 + w12 * y1,
                       w31 * z2 + w12 * z1, w31 + w12);
    red_v4(&g_acc[i1], w23 * x2 + w12 * x0, w23 * y2 + w12 * y0,
                       w23 * z2 + w12 * z0, w23 + w12);
    red_v4(&g_acc[i2], w23 * x1 + w31 * x0, w23 * y1 + w31 * y0,
                       w23 * z1 + w31 * z0, w23 + w31);
}

// out[v] = acc[v].xyz - acc[v].w * V[v], one thread per vertex
__global__ void fin_k(float* __restrict__ out) {
    int v = blockIdx.x * blockDim.x + threadIdx.x;
    if (v < BN) {
        float4 a = g_acc[v];
        float4 p = g_V4[v];
        float* o = out + (size_t)v * 3;
        o[0] = a.x - a.w * p.x;
        o[1] = a.y - a.w * p.y;
        o[2] = a.z - a.w * p.z;
    }
}

extern "C" void kernel_launch(void* const* d_in, const int* in_sizes, int n_in,
                              void* d_out, int out_size) {
    // Robust slot selection: V has BN*3 = 2.4M elements, F has TOTF*3 = 4.8M.
    const float* V;
    const void* F;
    int f_elems;
    if (in_sizes[0] == BN * 3) {
        V = (const float*)d_in[0];
        F = d_in[1];
        f_elems = in_sizes[1];
    } else {
        V = (const float*)d_in[1];
        F = d_in[0];
        f_elems = in_sizes[0];
    }
    float* out = (float*)d_out;

    detect_k<<<1, 32>>>((const long long*)F, f_elems / 2);
    prep_k<<<1024, 256>>>(V);
    face_k<<<(TOTF + 255) / 256, 256>>>(F);
    fin_k<<<(BN + 255) / 256, 256>>>(out);
}